// round 5
// baseline (speedup 1.0000x reference)
#include <cuda_runtime.h>
#include <cstdint>

#define Bz   8
#define Cc   512
#define Hh   96
#define Ww   96
#define HWp  9216
#define NPIX (Bz * HWp)
#define CKV  64

// Scratch (device globals: allocation-free per harness rules)
__device__ float g_k1[Bz * CKV * HWp];
__device__ float g_v [Bz * CKV * HWp];
__device__ float g_y [Bz * CKV * HWp];

// ---------------------------------------------------------------------------
// helpers
// ---------------------------------------------------------------------------
__device__ __forceinline__ uint32_t smem_u32(const void* p) {
    uint32_t a;
    asm("{ .reg .u64 t; cvta.to.shared.u64 t, %1; cvt.u32.u64 %0, t; }" : "=r"(a) : "l"(p));
    return a;
}
__device__ __forceinline__ uint32_t f2tf32(float f) {
    uint32_t r;
    asm("cvt.rna.tf32.f32 %0, %1;" : "=r"(r) : "f"(f));
    return r;
}
__device__ __forceinline__ void sts128(uint32_t a, uint32_t x, uint32_t y, uint32_t z, uint32_t w) {
    asm volatile("st.shared.v4.b32 [%0], {%1,%2,%3,%4};" :: "r"(a), "r"(x), "r"(y), "r"(z), "r"(w) : "memory");
}
__device__ __forceinline__ uint32_t lds32(uint32_t a) {
    uint32_t v;
    asm volatile("ld.shared.b32 %0, [%1];" : "=r"(v) : "r"(a));
    return v;
}
// Swizzled smem address: 128B rows (32 floats), 16B blocks XOR'd by row&7.
__device__ __forceinline__ uint32_t swaddr(uint32_t base, int row, int k) {
    return base + (uint32_t)(row * 128) + (uint32_t)((((k >> 2) ^ (row & 7)) << 4) + ((k & 3) << 2));
}
// D(16x8) += A(16x8,row) * B(8x8,col)  tf32
__device__ __forceinline__ void mma_tf32(float* d, const uint32_t* a, const uint32_t* b) {
    asm volatile(
        "mma.sync.aligned.m16n8k8.row.col.f32.tf32.tf32.f32 "
        "{%0,%1,%2,%3}, {%4,%5,%6,%7}, {%8,%9}, {%0,%1,%2,%3};"
        : "+f"(d[0]), "+f"(d[1]), "+f"(d[2]), "+f"(d[3])
        : "r"(a[0]), "r"(a[1]), "r"(a[2]), "r"(a[3]), "r"(b[0]), "r"(b[1]));
}

// ---------------------------------------------------------------------------
// Kernel 1: key1+value 1x1 convs. D[128ch][128pix], K=512, tf32 mma.sync.
//   grid = 576, block = 256 (8 warps, warp tile 64x32), dyn smem = 64KB
// ---------------------------------------------------------------------------
__global__ __launch_bounds__(256) void k1v_mma(
    const float* __restrict__ x,
    const float* __restrict__ k1w, const float* __restrict__ k1b,
    const float* __restrict__ vw,  const float* __restrict__ vb)
{
    extern __shared__ char smem[];
    const uint32_t sb = smem_u32(smem);

    const int t = threadIdx.x, warp = t >> 5, lane = t & 31;
    const int b = blockIdx.x / 72, hw0 = (blockIdx.x % 72) * 128;
    const float* xb = x + (size_t)b * Cc * HWp + hw0;

    const int arow = t >> 1, aq0 = (t & 1) * 4;
    const float* awsrc = (arow < 64) ? (k1w + (size_t)arow * Cc)
                                     : (vw  + (size_t)(arow - 64) * Cc);
    const int bp = t & 127, bq0 = (t >> 7) * 4;
    const int wm = (warp & 1) * 64, wn = (warp >> 1) * 32;

    float acc[4][4][4];
    #pragma unroll
    for (int i = 0; i < 4; i++)
        #pragma unroll
        for (int j = 0; j < 4; j++)
            #pragma unroll
            for (int q = 0; q < 4; q++) acc[i][j][q] = 0.f;

    float pa[16], pb[16];

    auto loadA = [&](int k0) {
        #pragma unroll
        for (int i = 0; i < 4; i++) {
            float4 v = *(const float4*)(awsrc + k0 + (aq0 + i) * 4);
            pa[i*4+0] = v.x; pa[i*4+1] = v.y; pa[i*4+2] = v.z; pa[i*4+3] = v.w;
        }
    };
    auto loadB = [&](int k0) {
        #pragma unroll
        for (int i = 0; i < 4; i++) {
            const float* s = xb + (size_t)(k0 + (bq0 + i) * 4) * HWp + bp;
            pb[i*4+0] = s[0]; pb[i*4+1] = s[HWp]; pb[i*4+2] = s[2*HWp]; pb[i*4+3] = s[3*HWp];
        }
    };
    auto store = [&](int buf) {
        uint32_t sA = sb + (uint32_t)buf * 32768u;
        uint32_t sB = sA + 16384u;
        #pragma unroll
        for (int i = 0; i < 4; i++) {
            sts128(swaddr(sA, arow, (aq0 + i) * 4),
                   f2tf32(pa[i*4+0]), f2tf32(pa[i*4+1]), f2tf32(pa[i*4+2]), f2tf32(pa[i*4+3]));
            sts128(swaddr(sB, bp, (bq0 + i) * 4),
                   f2tf32(pb[i*4+0]), f2tf32(pb[i*4+1]), f2tf32(pb[i*4+2]), f2tf32(pb[i*4+3]));
        }
    };
    auto compute = [&](int buf) {
        uint32_t sA = sb + (uint32_t)buf * 32768u;
        uint32_t sB = sA + 16384u;
        #pragma unroll
        for (int ks = 0; ks < 4; ks++) {
            const int kb = ks * 8;
            uint32_t af[4][4], bf[4][2];
            #pragma unroll
            for (int mi = 0; mi < 4; mi++) {
                int r = wm + mi * 16 + (lane >> 2);
                int c = kb + (lane & 3);
                af[mi][0] = lds32(swaddr(sA, r,     c));
                af[mi][1] = lds32(swaddr(sA, r + 8, c));
                af[mi][2] = lds32(swaddr(sA, r,     c + 4));
                af[mi][3] = lds32(swaddr(sA, r + 8, c + 4));
            }
            #pragma unroll
            for (int ni = 0; ni < 4; ni++) {
                int n = wn + ni * 8 + (lane >> 2);
                int c = kb + (lane & 3);
                bf[ni][0] = lds32(swaddr(sB, n, c));
                bf[ni][1] = lds32(swaddr(sB, n, c + 4));
            }
            #pragma unroll
            for (int mi = 0; mi < 4; mi++)
                #pragma unroll
                for (int ni = 0; ni < 4; ni++)
                    mma_tf32(acc[mi][ni], af[mi], bf[ni]);
        }
    };

    loadA(0); loadB(0); store(0);
    __syncthreads();
    for (int ck = 0; ck < 16; ck++) {
        if (ck < 15) { loadA((ck + 1) * 32); loadB((ck + 1) * 32); }
        compute(ck & 1);
        if (ck < 15) store((ck + 1) & 1);
        __syncthreads();
    }

    const bool iskey = (wm == 0);
    float* basep = iskey ? (g_k1 + (size_t)b * CKV * HWp) : (g_v + (size_t)b * CKV * HWp);
    #pragma unroll
    for (int mi = 0; mi < 4; mi++) {
        #pragma unroll
        for (int h = 0; h < 2; h++) {
            const int ch = mi * 16 + (lane >> 2) + h * 8;
            const float bias = iskey ? k1b[ch] : vb[ch];
            #pragma unroll
            for (int ni = 0; ni < 4; ni++) {
                const int n0 = hw0 + wn + ni * 8 + (lane & 3) * 2;
                float v0 = acc[mi][ni][h*2+0] + bias;
                float v1 = acc[mi][ni][h*2+1] + bias;
                if (iskey) { v0 = fmaxf(v0, 0.f); v1 = fmaxf(v1, 0.f); }
                float2 o = make_float2(v0, v1);
                *(float2*)(basep + (size_t)ch * HWp + n0) = o;
            }
        }
    }
}

// ---------------------------------------------------------------------------
// Kernel 2 (fused): depthwise 3x3 -> 1x1 64->9 -> softmax -> 9-tap gather.
//   Block = 32x8 pixel tile, 256 threads. All 64 channel tiles (10x36 with
//   halo) staged in smem; tap weights held in registers between phases.
//   grid = 8*36 = 288, dyn smem = 92160 B
// ---------------------------------------------------------------------------
#define TILE_ELEMS (10 * 36)          // per-channel tile with halo (rows 10, stride 36)
#define SMEM_MID   (CKV * TILE_ELEMS) // 23040 floats = 92160 B

__global__ __launch_bounds__(256) void mid_fused(
    const float* __restrict__ kdw_w, const float* __restrict__ kdw_b,
    const float* __restrict__ k3w,   const float* __restrict__ k3b)
{
    extern __shared__ float sm[];                 // [64][10][36]
    __shared__ float s_dw[CKV * 9];
    __shared__ float s_db[CKV];
    __shared__ float s_w3[9 * CKV];
    __shared__ float s_b3[9];

    const int t = threadIdx.x;
    for (int i = t; i < CKV * 9; i += 256) { s_dw[i] = kdw_w[i]; s_w3[i] = k3w[i]; }
    if (t < CKV) s_db[t] = kdw_b[t];
    if (t < 9)   s_b3[t] = k3b[t];

    const int bid  = blockIdx.x;
    const int b    = bid / 36;
    const int tile = bid % 36;
    const int h0   = (tile / 3) * 8;
    const int w0   = (tile % 3) * 32;
    const int ty   = t >> 5, tx = t & 31;         // pixel (h0+ty, w0+tx)

    // ---- Phase 1: stage k1 tiles (zero-padded halo) ----
    const float* k1base = g_k1 + (size_t)b * CKV * HWp;
    #pragma unroll 1
    for (int idx = t; idx < SMEM_MID; idx += 256) {
        int c  = idx / TILE_ELEMS;
        int r2 = idx % TILE_ELEMS;
        int rr = r2 / 36, cc = r2 % 36;
        int gh = h0 - 1 + rr, gw = w0 - 1 + cc;
        float v = 0.f;
        if (gh >= 0 && gh < Hh && gw >= 0 && gw < Ww && cc < 34)
            v = k1base[(size_t)c * HWp + gh * Ww + gw];
        sm[idx] = v;
    }
    __syncthreads();

    // ---- logits: depthwise 3x3 + 64->9 conv ----
    float logit[9];
    #pragma unroll
    for (int tt = 0; tt < 9; tt++) logit[tt] = s_b3[tt];

    #pragma unroll 4
    for (int c = 0; c < CKV; c++) {
        const float* tp = sm + c * TILE_ELEMS + ty * 36 + tx;
        float dw = s_db[c];
        #pragma unroll
        for (int dy = 0; dy < 3; dy++)
            #pragma unroll
            for (int dx = 0; dx < 3; dx++)
                dw = fmaf(tp[dy * 36 + dx], s_dw[c * 9 + dy * 3 + dx], dw);
        #pragma unroll
        for (int tt = 0; tt < 9; tt++)
            logit[tt] = fmaf(s_w3[tt * CKV + c], dw, logit[tt]);
    }

    // ---- softmax over taps (weights stay in registers) ----
    float m = logit[0];
    #pragma unroll
    for (int tt = 1; tt < 9; tt++) m = fmaxf(m, logit[tt]);
    float ws[9], s = 0.f;
    #pragma unroll
    for (int tt = 0; tt < 9; tt++) { ws[tt] = __expf(logit[tt] - m); s += ws[tt]; }
    float inv = 1.f / s;
    #pragma unroll
    for (int tt = 0; tt < 9; tt++) ws[tt] *= inv;

    // ---- Phase 2: stage v tiles (reuse smem), then 9-tap gather ----
    __syncthreads();
    const float* vbase = g_v + (size_t)b * CKV * HWp;
    #pragma unroll 1
    for (int idx = t; idx < SMEM_MID; idx += 256) {
        int c  = idx / TILE_ELEMS;
        int r2 = idx % TILE_ELEMS;
        int rr = r2 / 36, cc = r2 % 36;
        int gh = h0 - 1 + rr, gw = w0 - 1 + cc;
        float v = 0.f;
        if (gh >= 0 && gh < Hh && gw >= 0 && gw < Ww && cc < 34)
            v = vbase[(size_t)c * HWp + gh * Ww + gw];
        sm[idx] = v;
    }
    __syncthreads();

    float* yb = g_y + (size_t)b * CKV * HWp + (h0 + ty) * Ww + (w0 + tx);
    #pragma unroll 4
    for (int c = 0; c < CKV; c++) {
        const float* tp = sm + c * TILE_ELEMS + ty * 36 + tx;
        float acc = 0.f;
        #pragma unroll
        for (int dy = 0; dy < 3; dy++)
            #pragma unroll
            for (int dx = 0; dx < 3; dx++)
                acc = fmaf(ws[dy * 3 + dx], tp[dy * 36 + dx], acc);
        yb[(size_t)c * HWp] = acc;
    }
}

// ---------------------------------------------------------------------------
// Kernel 3: out 1x1 conv (512 co) + residual. D[128co][128pix], K=64, tf32 mma.
//   grid = (576, 4), block = 256, dyn smem = 64KB
// ---------------------------------------------------------------------------
__global__ __launch_bounds__(256) void out_mma(
    const float* __restrict__ x,
    const float* __restrict__ ow, const float* __restrict__ ob,
    float* __restrict__ out)
{
    extern __shared__ char smem[];
    const uint32_t sb = smem_u32(smem);

    const int t = threadIdx.x, warp = t >> 5, lane = t & 31;
    const int b = blockIdx.x / 72, hw0 = (blockIdx.x % 72) * 128;
    const int co0 = blockIdx.y * 128;
    const float* yb = g_y + (size_t)b * CKV * HWp + hw0;

    const int arow = t >> 1, aq0 = (t & 1) * 4;
    const float* awsrc = ow + (size_t)(co0 + arow) * CKV;
    const int bp = t & 127, bq0 = (t >> 7) * 4;
    const int wm = (warp & 1) * 64, wn = (warp >> 1) * 32;

    float acc[4][4][4];
    #pragma unroll
    for (int i = 0; i < 4; i++)
        #pragma unroll
        for (int j = 0; j < 4; j++)
            #pragma unroll
            for (int q = 0; q < 4; q++) acc[i][j][q] = 0.f;

    float pa[16], pb[16];
    auto loadA = [&](int k0) {
        #pragma unroll
        for (int i = 0; i < 4; i++) {
            float4 v = *(const float4*)(awsrc + k0 + (aq0 + i) * 4);
            pa[i*4+0] = v.x; pa[i*4+1] = v.y; pa[i*4+2] = v.z; pa[i*4+3] = v.w;
        }
    };
    auto loadB = [&](int k0) {
        #pragma unroll
        for (int i = 0; i < 4; i++) {
            const float* s = yb + (size_t)(k0 + (bq0 + i) * 4) * HWp + bp;
            pb[i*4+0] = s[0]; pb[i*4+1] = s[HWp]; pb[i*4+2] = s[2*HWp]; pb[i*4+3] = s[3*HWp];
        }
    };
    auto store = [&](int buf) {
        uint32_t sA = sb + (uint32_t)buf * 32768u;
        uint32_t sB = sA + 16384u;
        #pragma unroll
        for (int i = 0; i < 4; i++) {
            sts128(swaddr(sA, arow, (aq0 + i) * 4),
                   f2tf32(pa[i*4+0]), f2tf32(pa[i*4+1]), f2tf32(pa[i*4+2]), f2tf32(pa[i*4+3]));
            sts128(swaddr(sB, bp, (bq0 + i) * 4),
                   f2tf32(pb[i*4+0]), f2tf32(pb[i*4+1]), f2tf32(pb[i*4+2]), f2tf32(pb[i*4+3]));
        }
    };
    auto compute = [&](int buf) {
        uint32_t sA = sb + (uint32_t)buf * 32768u;
        uint32_t sB = sA + 16384u;
        #pragma unroll
        for (int ks = 0; ks < 4; ks++) {
            const int kb = ks * 8;
            uint32_t af[4][4], bf[4][2];
            #pragma unroll
            for (int mi = 0; mi < 4; mi++) {
                int r = wm + mi * 16 + (lane >> 2);
                int c = kb + (lane & 3);
                af[mi][0] = lds32(swaddr(sA, r,     c));
                af[mi][1] = lds32(swaddr(sA, r + 8, c));
                af[mi][2] = lds32(swaddr(sA, r,     c + 4));
                af[mi][3] = lds32(swaddr(sA, r + 8, c + 4));
            }
            #pragma unroll
            for (int ni = 0; ni < 4; ni++) {
                int n = wn + ni * 8 + (lane >> 2);
                int c = kb + (lane & 3);
                bf[ni][0] = lds32(swaddr(sB, n, c));
                bf[ni][1] = lds32(swaddr(sB, n, c + 4));
            }
            #pragma unroll
            for (int mi = 0; mi < 4; mi++)
                #pragma unroll
                for (int ni = 0; ni < 4; ni++)
                    mma_tf32(acc[mi][ni], af[mi], bf[ni]);
        }
    };

    loadA(0); loadB(0); store(0);
    __syncthreads();
    for (int ck = 0; ck < 2; ck++) {
        if (ck < 1) { loadA(32); loadB(32); }
        compute(ck & 1);
        if (ck < 1) store(1);
        __syncthreads();
    }

    #pragma unroll
    for (int mi = 0; mi < 4; mi++) {
        #pragma unroll
        for (int h = 0; h < 2; h++) {
            const int co = co0 + wm + mi * 16 + (lane >> 2) + h * 8;
            const float bias = ob[co];
            #pragma unroll
            for (int ni = 0; ni < 4; ni++) {
                const int n0 = hw0 + wn + ni * 8 + (lane & 3) * 2;
                const size_t idx = ((size_t)b * Cc + co) * HWp + n0;
                float2 xv = *(const float2*)(x + idx);
                float2 o;
                o.x = xv.x + bias + acc[mi][ni][h*2+0];
                o.y = xv.y + bias + acc[mi][ni][h*2+1];
                *(float2*)(out + idx) = o;
            }
        }
    }
}

// ---------------------------------------------------------------------------
extern "C" void kernel_launch(void* const* d_in, const int* in_sizes, int n_in,
                              void* d_out, int out_size)
{
    const float* x      = (const float*)d_in[0];
    const float* key1_w = (const float*)d_in[1];
    const float* key1_b = (const float*)d_in[2];
    const float* kdw_w  = (const float*)d_in[3];
    const float* kdw_b  = (const float*)d_in[4];
    const float* key3_w = (const float*)d_in[5];
    const float* key3_b = (const float*)d_in[6];
    const float* val_w  = (const float*)d_in[7];
    const float* val_b  = (const float*)d_in[8];
    const float* out_w  = (const float*)d_in[9];
    const float* out_b  = (const float*)d_in[10];
    float* out = (float*)d_out;

    static bool attr_set = false;
    if (!attr_set) {
        cudaFuncSetAttribute(k1v_mma,   cudaFuncAttributeMaxDynamicSharedMemorySize, 65536);
        cudaFuncSetAttribute(out_mma,   cudaFuncAttributeMaxDynamicSharedMemorySize, 65536);
        cudaFuncSetAttribute(mid_fused, cudaFuncAttributeMaxDynamicSharedMemorySize, SMEM_MID * 4);
        attr_set = true;
    }

    k1v_mma<<<576, 256, 65536>>>(x, key1_w, key1_b, val_w, val_b);
    mid_fused<<<Bz * 36, 256, SMEM_MID * 4>>>(kdw_w, kdw_b, key3_w, key3_b);
    out_mma<<<dim3(576, 4), 256, 65536>>>(x, out_w, out_b, out);
}

// round 7
// speedup vs baseline: 1.4595x; 1.4595x over previous
#include <cuda_runtime.h>
#include <cuda_bf16.h>
#include <cstdint>

#define Bz   8
#define Cc   512
#define Hh   96
#define Ww   96
#define HWp  9216
#define NPIX (Bz * HWp)
#define CKV  64

// Scratch (device globals: allocation-free per harness rules)
__device__ float g_k1[Bz * CKV * HWp];
__device__ float g_v [Bz * CKV * HWp];
__device__ float g_y [Bz * CKV * HWp];

// ---------------------------------------------------------------------------
// helpers
// ---------------------------------------------------------------------------
__device__ __forceinline__ uint32_t smem_u32(const void* p) {
    uint32_t a;
    asm("{ .reg .u64 t; cvta.to.shared.u64 t, %1; cvt.u32.u64 %0, t; }" : "=r"(a) : "l"(p));
    return a;
}
__device__ __forceinline__ uint32_t f2tf32(float f) {
    uint32_t r;
    asm("cvt.rna.tf32.f32 %0, %1;" : "=r"(r) : "f"(f));
    return r;
}
__device__ __forceinline__ uint32_t pk_bf16(float a, float b) {
    __nv_bfloat162 h = __floats2bfloat162_rn(a, b);   // low = a, high = b
    return *(uint32_t*)&h;
}
__device__ __forceinline__ void sts128(uint32_t a, uint32_t x, uint32_t y, uint32_t z, uint32_t w) {
    asm volatile("st.shared.v4.b32 [%0], {%1,%2,%3,%4};" :: "r"(a), "r"(x), "r"(y), "r"(z), "r"(w) : "memory");
}
__device__ __forceinline__ uint32_t lds32(uint32_t a) {
    uint32_t v;
    asm volatile("ld.shared.b32 %0, [%1];" : "=r"(v) : "r"(a));
    return v;
}
#define LDMATRIX_X4(r0, r1, r2, r3, addr) \
    asm volatile("ldmatrix.sync.aligned.m8n8.x4.shared.b16 {%0,%1,%2,%3}, [%4];" \
                 : "=r"(r0), "=r"(r1), "=r"(r2), "=r"(r3) : "r"(addr))

// fp32-element swizzled addr: 128B rows (32 floats), 16B blocks XOR'd by row&7.
__device__ __forceinline__ uint32_t swaddr(uint32_t base, int row, int k) {
    return base + (uint32_t)(row * 128) + (uint32_t)((((k >> 2) ^ (row & 7)) << 4) + ((k & 3) << 2));
}
// bf16-element swizzled addr: 128B rows (64 halves), 16B blocks (8 halves) XOR'd by row&7.
__device__ __forceinline__ uint32_t swaddr_h(uint32_t base, int row, int k) {
    return base + (uint32_t)(row * 128) + (uint32_t)((((k >> 3) ^ (row & 7)) << 4) + ((k & 7) << 1));
}
// D(16x8) += A(16x8,row) * B(8x8,col)  tf32
__device__ __forceinline__ void mma_tf32(float* d, const uint32_t* a, const uint32_t* b) {
    asm volatile(
        "mma.sync.aligned.m16n8k8.row.col.f32.tf32.tf32.f32 "
        "{%0,%1,%2,%3}, {%4,%5,%6,%7}, {%8,%9}, {%0,%1,%2,%3};"
        : "+f"(d[0]), "+f"(d[1]), "+f"(d[2]), "+f"(d[3])
        : "r"(a[0]), "r"(a[1]), "r"(a[2]), "r"(a[3]), "r"(b[0]), "r"(b[1]));
}
// D(16x8) += A(16x16,row) * B(16x8,col)  bf16
__device__ __forceinline__ void mma_bf16(float* d, const uint32_t* a, uint32_t b0, uint32_t b1) {
    asm volatile(
        "mma.sync.aligned.m16n8k16.row.col.f32.bf16.bf16.f32 "
        "{%0,%1,%2,%3}, {%4,%5,%6,%7}, {%8,%9}, {%0,%1,%2,%3};"
        : "+f"(d[0]), "+f"(d[1]), "+f"(d[2]), "+f"(d[3])
        : "r"(a[0]), "r"(a[1]), "r"(a[2]), "r"(a[3]), "r"(b0), "r"(b1));
}

// ---------------------------------------------------------------------------
// Kernel 1: key1+value 1x1 convs. D[128ch][128pix], K=512, bf16 mma + ldmatrix.
//   grid = 576, block = 256 (8 warps, warp tile 64x32), dyn smem = 64KB
// ---------------------------------------------------------------------------
__global__ __launch_bounds__(256) void k1v_mma(
    const float* __restrict__ x,
    const float* __restrict__ k1w, const float* __restrict__ k1b,
    const float* __restrict__ vw,  const float* __restrict__ vb)
{
    extern __shared__ char smem[];
    const uint32_t sb = smem_u32(smem);

    const int t = threadIdx.x, warp = t >> 5, lane = t & 31;
    const int b = blockIdx.x / 72, hw0 = (blockIdx.x % 72) * 128;
    const float* xb = x + (size_t)b * Cc * HWp + hw0;

    // A-load: row = t/2 (128 weight rows), 16 floats at (t&1)*16
    const int arow = t >> 1, ak0 = (t & 1) * 16;
    const float* awsrc = (arow < 64) ? (k1w + (size_t)arow * Cc)
                                     : (vw  + (size_t)(arow - 64) * Cc);
    // B-load: pixel p = t%128, 16 k-floats at (t/128)*16 (transpose store)
    const int bp = t & 127, bk0 = (t >> 7) * 16;
    const int wm = (warp & 1) * 64, wn = (warp >> 1) * 32;

    float acc[4][4][4];
    #pragma unroll
    for (int i = 0; i < 4; i++)
        #pragma unroll
        for (int j = 0; j < 4; j++)
            #pragma unroll
            for (int q = 0; q < 4; q++) acc[i][j][q] = 0.f;

    float pa[16], pb[16];

    auto loadA = [&](int k0) {
        #pragma unroll
        for (int i = 0; i < 4; i++) {
            float4 v = *(const float4*)(awsrc + k0 + ak0 + i * 4);
            pa[i*4+0] = v.x; pa[i*4+1] = v.y; pa[i*4+2] = v.z; pa[i*4+3] = v.w;
        }
    };
    auto loadB = [&](int k0) {
        const float* s = xb + (size_t)(k0 + bk0) * HWp + bp;
        #pragma unroll
        for (int i = 0; i < 16; i++) pb[i] = s[(size_t)i * HWp];
    };
    auto store = [&](int buf) {
        uint32_t sA = sb + (uint32_t)buf * 32768u;
        uint32_t sB = sA + 16384u;
        #pragma unroll
        for (int i = 0; i < 2; i++) {
            sts128(swaddr_h(sA, arow, ak0 + i * 8),
                   pk_bf16(pa[i*8+0], pa[i*8+1]), pk_bf16(pa[i*8+2], pa[i*8+3]),
                   pk_bf16(pa[i*8+4], pa[i*8+5]), pk_bf16(pa[i*8+6], pa[i*8+7]));
            sts128(swaddr_h(sB, bp, bk0 + i * 8),
                   pk_bf16(pb[i*8+0], pb[i*8+1]), pk_bf16(pb[i*8+2], pb[i*8+3]),
                   pk_bf16(pb[i*8+4], pb[i*8+5]), pk_bf16(pb[i*8+6], pb[i*8+7]));
        }
    };
    auto compute = [&](int buf) {
        uint32_t sA = sb + (uint32_t)buf * 32768u;
        uint32_t sB = sA + 16384u;
        #pragma unroll
        for (int ks = 0; ks < 2; ks++) {
            const int kb = ks * 16 + ((lane >> 4) << 3);   // per-lane k block
            uint32_t af[4][4], bf[4][2];
            #pragma unroll
            for (int mi = 0; mi < 4; mi++)
                LDMATRIX_X4(af[mi][0], af[mi][1], af[mi][2], af[mi][3],
                            swaddr_h(sA, wm + mi * 16 + (lane & 15), kb));
            #pragma unroll
            for (int nh = 0; nh < 2; nh++) {
                uint32_t m0, m1, m2, m3;
                LDMATRIX_X4(m0, m1, m2, m3,
                            swaddr_h(sB, wn + nh * 16 + (lane & 15), kb));
                bf[nh*2+0][0] = m0; bf[nh*2+0][1] = m2;
                bf[nh*2+1][0] = m1; bf[nh*2+1][1] = m3;
            }
            #pragma unroll
            for (int mi = 0; mi < 4; mi++)
                #pragma unroll
                for (int ni = 0; ni < 4; ni++)
                    mma_bf16(acc[mi][ni], af[mi], bf[ni][0], bf[ni][1]);
        }
    };

    loadA(0); loadB(0); store(0);
    __syncthreads();
    for (int ck = 0; ck < 16; ck++) {
        if (ck < 15) { loadA((ck + 1) * 32); loadB((ck + 1) * 32); }
        compute(ck & 1);
        if (ck < 15) store((ck + 1) & 1);
        __syncthreads();
    }

    const bool iskey = (wm == 0);
    float* basep = iskey ? (g_k1 + (size_t)b * CKV * HWp) : (g_v + (size_t)b * CKV * HWp);
    #pragma unroll
    for (int mi = 0; mi < 4; mi++) {
        #pragma unroll
        for (int h = 0; h < 2; h++) {
            const int ch = mi * 16 + (lane >> 2) + h * 8;
            const float bias = iskey ? k1b[ch] : vb[ch];
            #pragma unroll
            for (int ni = 0; ni < 4; ni++) {
                const int n0 = hw0 + wn + ni * 8 + (lane & 3) * 2;
                float v0 = acc[mi][ni][h*2+0] + bias;
                float v1 = acc[mi][ni][h*2+1] + bias;
                if (iskey) { v0 = fmaxf(v0, 0.f); v1 = fmaxf(v1, 0.f); }
                float2 o = make_float2(v0, v1);
                *(float2*)(basep + (size_t)ch * HWp + n0) = o;
            }
        }
    }
}

// ---------------------------------------------------------------------------
// Kernel 2 (fused): depthwise 3x3 -> 1x1 64->9 -> softmax -> 9-tap gather.
//   Block = 32x8 pixel tile. Staging loops batched (MLP=6).
//   grid = 8*36 = 288, dyn smem = 92160 B
// ---------------------------------------------------------------------------
#define TILE_ELEMS (10 * 36)
#define SMEM_MID   (CKV * TILE_ELEMS)   // 23040 floats

__global__ __launch_bounds__(256) void mid_fused(
    const float* __restrict__ kdw_w, const float* __restrict__ kdw_b,
    const float* __restrict__ k3w,   const float* __restrict__ k3b)
{
    extern __shared__ float sm[];                 // [64][10][36]
    __shared__ float s_dw[CKV * 9];
    __shared__ float s_db[CKV];
    __shared__ float s_w3[9 * CKV];
    __shared__ float s_b3[9];

    const int t = threadIdx.x;
    for (int i = t; i < CKV * 9; i += 256) { s_dw[i] = kdw_w[i]; s_w3[i] = k3w[i]; }
    if (t < CKV) s_db[t] = kdw_b[t];
    if (t < 9)   s_b3[t] = k3b[t];

    const int bid  = blockIdx.x;
    const int b    = bid / 36;
    const int tile = bid % 36;
    const int h0   = (tile / 3) * 8;
    const int w0   = (tile % 3) * 32;
    const int ty   = t >> 5, tx = t & 31;

    // Batched staging: 90 elements per thread, groups of 6 LDG in flight.
    auto stage = [&](const float* __restrict__ basep) {
        #pragma unroll 1
        for (int g = 0; g < 90; g += 6) {
            float vals[6];
            #pragma unroll
            for (int j = 0; j < 6; j++) {
                int idx = (g + j) * 256 + t;
                int c   = idx / TILE_ELEMS;
                int r2  = idx - c * TILE_ELEMS;
                int rr  = r2 / 36, cc = r2 - rr * 36;
                int gh  = h0 - 1 + rr, gw = w0 - 1 + cc;
                bool ok = (gh >= 0) & (gh < Hh) & (gw >= 0) & (gw < Ww) & (cc < 34);
                vals[j] = ok ? basep[(size_t)c * HWp + gh * Ww + gw] : 0.f;
            }
            #pragma unroll
            for (int j = 0; j < 6; j++) sm[(g + j) * 256 + t] = vals[j];
        }
    };

    // ---- Phase 1: stage k1, compute logits ----
    stage(g_k1 + (size_t)b * CKV * HWp);
    __syncthreads();

    float logit[9];
    #pragma unroll
    for (int tt = 0; tt < 9; tt++) logit[tt] = s_b3[tt];

    #pragma unroll 4
    for (int c = 0; c < CKV; c++) {
        const float* tp = sm + c * TILE_ELEMS + ty * 36 + tx;
        float dw = s_db[c];
        #pragma unroll
        for (int dy = 0; dy < 3; dy++)
            #pragma unroll
            for (int dx = 0; dx < 3; dx++)
                dw = fmaf(tp[dy * 36 + dx], s_dw[c * 9 + dy * 3 + dx], dw);
        #pragma unroll
        for (int tt = 0; tt < 9; tt++)
            logit[tt] = fmaf(s_w3[tt * CKV + c], dw, logit[tt]);
    }

    float m = logit[0];
    #pragma unroll
    for (int tt = 1; tt < 9; tt++) m = fmaxf(m, logit[tt]);
    float ws[9], s = 0.f;
    #pragma unroll
    for (int tt = 0; tt < 9; tt++) { ws[tt] = __expf(logit[tt] - m); s += ws[tt]; }
    float inv = 1.f / s;
    #pragma unroll
    for (int tt = 0; tt < 9; tt++) ws[tt] *= inv;

    // ---- Phase 2: stage v, 9-tap gather ----
    __syncthreads();
    stage(g_v + (size_t)b * CKV * HWp);
    __syncthreads();

    float* yb = g_y + (size_t)b * CKV * HWp + (h0 + ty) * Ww + (w0 + tx);
    #pragma unroll 4
    for (int c = 0; c < CKV; c++) {
        const float* tp = sm + c * TILE_ELEMS + ty * 36 + tx;
        float acc = 0.f;
        #pragma unroll
        for (int dy = 0; dy < 3; dy++)
            #pragma unroll
            for (int dx = 0; dx < 3; dx++)
                acc = fmaf(ws[dy * 3 + dx], tp[dy * 36 + dx], acc);
        yb[(size_t)c * HWp] = acc;
    }
}

// ---------------------------------------------------------------------------
// Kernel 3: out 1x1 conv (512 co) + residual. D[128co][128pix], K=64, tf32 mma.
//   (kept tf32 — DRAM-bound; protects precision)
//   grid = (576, 4), block = 256, dyn smem = 64KB
// ---------------------------------------------------------------------------
__global__ __launch_bounds__(256) void out_mma(
    const float* __restrict__ x,
    const float* __restrict__ ow, const float* __restrict__ ob,
    float* __restrict__ out)
{
    extern __shared__ char smem[];
    const uint32_t sb = smem_u32(smem);

    const int t = threadIdx.x, warp = t >> 5, lane = t & 31;
    const int b = blockIdx.x / 72, hw0 = (blockIdx.x % 72) * 128;
    const int co0 = blockIdx.y * 128;
    const float* yb = g_y + (size_t)b * CKV * HWp + hw0;

    const int arow = t >> 1, aq0 = (t & 1) * 4;
    const float* awsrc = ow + (size_t)(co0 + arow) * CKV;
    const int bp = t & 127, bq0 = (t >> 7) * 4;
    const int wm = (warp & 1) * 64, wn = (warp >> 1) * 32;

    float acc[4][4][4];
    #pragma unroll
    for (int i = 0; i < 4; i++)
        #pragma unroll
        for (int j = 0; j < 4; j++)
            #pragma unroll
            for (int q = 0; q < 4; q++) acc[i][j][q] = 0.f;

    float pa[16], pb[16];
    auto loadA = [&](int k0) {
        #pragma unroll
        for (int i = 0; i < 4; i++) {
            float4 v = *(const float4*)(awsrc + k0 + (aq0 + i) * 4);
            pa[i*4+0] = v.x; pa[i*4+1] = v.y; pa[i*4+2] = v.z; pa[i*4+3] = v.w;
        }
    };
    auto loadB = [&](int k0) {
        #pragma unroll
        for (int i = 0; i < 4; i++) {
            const float* s = yb + (size_t)(k0 + (bq0 + i) * 4) * HWp + bp;
            pb[i*4+0] = s[0]; pb[i*4+1] = s[HWp]; pb[i*4+2] = s[2*HWp]; pb[i*4+3] = s[3*HWp];
        }
    };
    auto store = [&](int buf) {
        uint32_t sA = sb + (uint32_t)buf * 32768u;
        uint32_t sB = sA + 16384u;
        #pragma unroll
        for (int i = 0; i < 4; i++) {
            sts128(swaddr(sA, arow, (aq0 + i) * 4),
                   f2tf32(pa[i*4+0]), f2tf32(pa[i*4+1]), f2tf32(pa[i*4+2]), f2tf32(pa[i*4+3]));
            sts128(swaddr(sB, bp, (bq0 + i) * 4),
                   f2tf32(pb[i*4+0]), f2tf32(pb[i*4+1]), f2tf32(pb[i*4+2]), f2tf32(pb[i*4+3]));
        }
    };
    auto compute = [&](int buf) {
        uint32_t sA = sb + (uint32_t)buf * 32768u;
        uint32_t sB = sA + 16384u;
        #pragma unroll
        for (int ks = 0; ks < 4; ks++) {
            const int kb = ks * 8;
            uint32_t af[4][4], bf[4][2];
            #pragma unroll
            for (int mi = 0; mi < 4; mi++) {
                int r = wm + mi * 16 + (lane >> 2);
                int c = kb + (lane & 3);
                af[mi][0] = lds32(swaddr(sA, r,     c));
                af[mi][1] = lds32(swaddr(sA, r + 8, c));
                af[mi][2] = lds32(swaddr(sA, r,     c + 4));
                af[mi][3] = lds32(swaddr(sA, r + 8, c + 4));
            }
            #pragma unroll
            for (int ni = 0; ni < 4; ni++) {
                int n = wn + ni * 8 + (lane >> 2);
                int c = kb + (lane & 3);
                bf[ni][0] = lds32(swaddr(sB, n, c));
                bf[ni][1] = lds32(swaddr(sB, n, c + 4));
            }
            #pragma unroll
            for (int mi = 0; mi < 4; mi++)
                #pragma unroll
                for (int ni = 0; ni < 4; ni++)
                    mma_tf32(acc[mi][ni], af[mi], bf[ni]);
        }
    };

    loadA(0); loadB(0); store(0);
    __syncthreads();
    for (int ck = 0; ck < 2; ck++) {
        if (ck < 1) { loadA(32); loadB(32); }
        compute(ck & 1);
        if (ck < 1) store(1);
        __syncthreads();
    }

    #pragma unroll
    for (int mi = 0; mi < 4; mi++) {
        #pragma unroll
        for (int h = 0; h < 2; h++) {
            const int co = co0 + wm + mi * 16 + (lane >> 2) + h * 8;
            const float bias = ob[co];
            #pragma unroll
            for (int ni = 0; ni < 4; ni++) {
                const int n0 = hw0 + wn + ni * 8 + (lane & 3) * 2;
                const size_t idx = ((size_t)b * Cc + co) * HWp + n0;
                float2 xv = *(const float2*)(x + idx);
                float2 o;
                o.x = xv.x + bias + acc[mi][ni][h*2+0];
                o.y = xv.y + bias + acc[mi][ni][h*2+1];
                *(float2*)(out + idx) = o;
            }
        }
    }
}

// ---------------------------------------------------------------------------
extern "C" void kernel_launch(void* const* d_in, const int* in_sizes, int n_in,
                              void* d_out, int out_size)
{
    const float* x      = (const float*)d_in[0];
    const float* key1_w = (const float*)d_in[1];
    const float* key1_b = (const float*)d_in[2];
    const float* kdw_w  = (const float*)d_in[3];
    const float* kdw_b  = (const float*)d_in[4];
    const float* key3_w = (const float*)d_in[5];
    const float* key3_b = (const float*)d_in[6];
    const float* val_w  = (const float*)d_in[7];
    const float* val_b  = (const float*)d_in[8];
    const float* out_w  = (const float*)d_in[9];
    const float* out_b  = (const float*)d_in[10];
    float* out = (float*)d_out;

    static bool attr_set = false;
    if (!attr_set) {
        cudaFuncSetAttribute(k1v_mma,   cudaFuncAttributeMaxDynamicSharedMemorySize, 65536);
        cudaFuncSetAttribute(out_mma,   cudaFuncAttributeMaxDynamicSharedMemorySize, 65536);
        cudaFuncSetAttribute(mid_fused, cudaFuncAttributeMaxDynamicSharedMemorySize, SMEM_MID * 4);
        attr_set = true;
    }

    k1v_mma<<<576, 256, 65536>>>(x, key1_w, key1_b, val_w, val_b);
    mid_fused<<<Bz * 36, 256, SMEM_MID * 4>>>(kdw_w, kdw_b, key3_w, key3_b);
    out_mma<<<dim3(576, 4), 256, 65536>>>(x, out_w, out_b, out);
}

// round 9
// speedup vs baseline: 1.5276x; 1.0466x over previous
#include <cuda_runtime.h>
#include <cuda_bf16.h>
#include <cstdint>

#define Bz   8
#define Cc   512
#define Hh   96
#define Ww   96
#define HWp  9216
#define NPIX (Bz * HWp)
#define CKV  64

// Scratch (device globals: allocation-free per harness rules)
__device__ float g_k1[Bz * CKV * HWp];
__device__ float g_v [Bz * CKV * HWp];
__device__ float g_y [Bz * CKV * HWp];

// ---------------------------------------------------------------------------
// helpers
// ---------------------------------------------------------------------------
__device__ __forceinline__ uint32_t smem_u32(const void* p) {
    uint32_t a;
    asm("{ .reg .u64 t; cvta.to.shared.u64 t, %1; cvt.u32.u64 %0, t; }" : "=r"(a) : "l"(p));
    return a;
}
__device__ __forceinline__ uint32_t f2tf32(float f) {
    uint32_t r;
    asm("cvt.rna.tf32.f32 %0, %1;" : "=r"(r) : "f"(f));
    return r;
}
__device__ __forceinline__ uint32_t pk_bf16(float a, float b) {
    __nv_bfloat162 h = __floats2bfloat162_rn(a, b);   // low = a, high = b
    return *(uint32_t*)&h;
}
__device__ __forceinline__ void sts128(uint32_t a, uint32_t x, uint32_t y, uint32_t z, uint32_t w) {
    asm volatile("st.shared.v4.b32 [%0], {%1,%2,%3,%4};" :: "r"(a), "r"(x), "r"(y), "r"(z), "r"(w) : "memory");
}
__device__ __forceinline__ uint32_t lds32(uint32_t a) {
    uint32_t v;
    asm volatile("ld.shared.b32 %0, [%1];" : "=r"(v) : "r"(a));
    return v;
}
#define LDMATRIX_X4(r0, r1, r2, r3, addr) \
    asm volatile("ldmatrix.sync.aligned.m8n8.x4.shared.b16 {%0,%1,%2,%3}, [%4];" \
                 : "=r"(r0), "=r"(r1), "=r"(r2), "=r"(r3) : "r"(addr))

// fp32-element swizzled addr: 128B rows (32 floats), 16B blocks XOR'd by row&7.
__device__ __forceinline__ uint32_t swaddr(uint32_t base, int row, int k) {
    return base + (uint32_t)(row * 128) + (uint32_t)((((k >> 2) ^ (row & 7)) << 4) + ((k & 3) << 2));
}
// bf16-element swizzled addr: 128B rows (64 halves), 16B blocks (8 halves) XOR'd by row&7.
__device__ __forceinline__ uint32_t swaddr_h(uint32_t base, int row, int k) {
    return base + (uint32_t)(row * 128) + (uint32_t)((((k >> 3) ^ (row & 7)) << 4) + ((k & 7) << 1));
}
// D(16x8) += A(16x8,row) * B(8x8,col)  tf32
__device__ __forceinline__ void mma_tf32(float* d, const uint32_t* a, const uint32_t* b) {
    asm volatile(
        "mma.sync.aligned.m16n8k8.row.col.f32.tf32.tf32.f32 "
        "{%0,%1,%2,%3}, {%4,%5,%6,%7}, {%8,%9}, {%0,%1,%2,%3};"
        : "+f"(d[0]), "+f"(d[1]), "+f"(d[2]), "+f"(d[3])
        : "r"(a[0]), "r"(a[1]), "r"(a[2]), "r"(a[3]), "r"(b[0]), "r"(b[1]));
}
// D(16x8) += A(16x16,row) * B(16x8,col)  bf16
__device__ __forceinline__ void mma_bf16(float* d, const uint32_t* a, uint32_t b0, uint32_t b1) {
    asm volatile(
        "mma.sync.aligned.m16n8k16.row.col.f32.bf16.bf16.f32 "
        "{%0,%1,%2,%3}, {%4,%5,%6,%7}, {%8,%9}, {%0,%1,%2,%3};"
        : "+f"(d[0]), "+f"(d[1]), "+f"(d[2]), "+f"(d[3])
        : "r"(a[0]), "r"(a[1]), "r"(a[2]), "r"(a[3]), "r"(b0), "r"(b1));
}

// ---------------------------------------------------------------------------
// Kernel 1: key1+value 1x1 convs. D[128ch][128pix], K=512, bf16 mma + ldmatrix.
//   grid = 576, block = 256 (8 warps, warp tile 64x32), dyn smem = 64KB
//   (unchanged from R7)
// ---------------------------------------------------------------------------
__global__ __launch_bounds__(256) void k1v_mma(
    const float* __restrict__ x,
    const float* __restrict__ k1w, const float* __restrict__ k1b,
    const float* __restrict__ vw,  const float* __restrict__ vb)
{
    extern __shared__ char smem[];
    const uint32_t sb = smem_u32(smem);

    const int t = threadIdx.x, warp = t >> 5, lane = t & 31;
    const int b = blockIdx.x / 72, hw0 = (blockIdx.x % 72) * 128;
    const float* xb = x + (size_t)b * Cc * HWp + hw0;

    const int arow = t >> 1, ak0 = (t & 1) * 16;
    const float* awsrc = (arow < 64) ? (k1w + (size_t)arow * Cc)
                                     : (vw  + (size_t)(arow - 64) * Cc);
    const int bp = t & 127, bk0 = (t >> 7) * 16;
    const int wm = (warp & 1) * 64, wn = (warp >> 1) * 32;

    float acc[4][4][4];
    #pragma unroll
    for (int i = 0; i < 4; i++)
        #pragma unroll
        for (int j = 0; j < 4; j++)
            #pragma unroll
            for (int q = 0; q < 4; q++) acc[i][j][q] = 0.f;

    float pa[16], pb[16];

    auto loadA = [&](int k0) {
        #pragma unroll
        for (int i = 0; i < 4; i++) {
            float4 v = *(const float4*)(awsrc + k0 + ak0 + i * 4);
            pa[i*4+0] = v.x; pa[i*4+1] = v.y; pa[i*4+2] = v.z; pa[i*4+3] = v.w;
        }
    };
    auto loadB = [&](int k0) {
        const float* s = xb + (size_t)(k0 + bk0) * HWp + bp;
        #pragma unroll
        for (int i = 0; i < 16; i++) pb[i] = s[(size_t)i * HWp];
    };
    auto store = [&](int buf) {
        uint32_t sA = sb + (uint32_t)buf * 32768u;
        uint32_t sB = sA + 16384u;
        #pragma unroll
        for (int i = 0; i < 2; i++) {
            sts128(swaddr_h(sA, arow, ak0 + i * 8),
                   pk_bf16(pa[i*8+0], pa[i*8+1]), pk_bf16(pa[i*8+2], pa[i*8+3]),
                   pk_bf16(pa[i*8+4], pa[i*8+5]), pk_bf16(pa[i*8+6], pa[i*8+7]));
            sts128(swaddr_h(sB, bp, bk0 + i * 8),
                   pk_bf16(pb[i*8+0], pb[i*8+1]), pk_bf16(pb[i*8+2], pb[i*8+3]),
                   pk_bf16(pb[i*8+4], pb[i*8+5]), pk_bf16(pb[i*8+6], pb[i*8+7]));
        }
    };
    auto compute = [&](int buf) {
        uint32_t sA = sb + (uint32_t)buf * 32768u;
        uint32_t sB = sA + 16384u;
        #pragma unroll
        for (int ks = 0; ks < 2; ks++) {
            const int kb = ks * 16 + ((lane >> 4) << 3);
            uint32_t af[4][4], bf[4][2];
            #pragma unroll
            for (int mi = 0; mi < 4; mi++)
                LDMATRIX_X4(af[mi][0], af[mi][1], af[mi][2], af[mi][3],
                            swaddr_h(sA, wm + mi * 16 + (lane & 15), kb));
            #pragma unroll
            for (int nh = 0; nh < 2; nh++) {
                uint32_t m0, m1, m2, m3;
                LDMATRIX_X4(m0, m1, m2, m3,
                            swaddr_h(sB, wn + nh * 16 + (lane & 15), kb));
                bf[nh*2+0][0] = m0; bf[nh*2+0][1] = m2;
                bf[nh*2+1][0] = m1; bf[nh*2+1][1] = m3;
            }
            #pragma unroll
            for (int mi = 0; mi < 4; mi++)
                #pragma unroll
                for (int ni = 0; ni < 4; ni++)
                    mma_bf16(acc[mi][ni], af[mi], bf[ni][0], bf[ni][1]);
        }
    };

    loadA(0); loadB(0); store(0);
    __syncthreads();
    for (int ck = 0; ck < 16; ck++) {
        if (ck < 15) { loadA((ck + 1) * 32); loadB((ck + 1) * 32); }
        compute(ck & 1);
        if (ck < 15) store((ck + 1) & 1);
        __syncthreads();
    }

    const bool iskey = (wm == 0);
    float* basep = iskey ? (g_k1 + (size_t)b * CKV * HWp) : (g_v + (size_t)b * CKV * HWp);
    #pragma unroll
    for (int mi = 0; mi < 4; mi++) {
        #pragma unroll
        for (int h = 0; h < 2; h++) {
            const int ch = mi * 16 + (lane >> 2) + h * 8;
            const float bias = iskey ? k1b[ch] : vb[ch];
            #pragma unroll
            for (int ni = 0; ni < 4; ni++) {
                const int n0 = hw0 + wn + ni * 8 + (lane & 3) * 2;
                float v0 = acc[mi][ni][h*2+0] + bias;
                float v1 = acc[mi][ni][h*2+1] + bias;
                if (iskey) { v0 = fmaxf(v0, 0.f); v1 = fmaxf(v1, 0.f); }
                float2 o = make_float2(v0, v1);
                *(float2*)(basep + (size_t)ch * HWp + n0) = o;
            }
        }
    }
}

// ---------------------------------------------------------------------------
// Kernel 2 (fused): depthwise 3x3 -> 1x1 64->9 -> softmax -> 9-tap gather.
//   (unchanged from R7)
// ---------------------------------------------------------------------------
#define TILE_ELEMS (10 * 36)
#define SMEM_MID   (CKV * TILE_ELEMS)   // 23040 floats

__global__ __launch_bounds__(256) void mid_fused(
    const float* __restrict__ kdw_w, const float* __restrict__ kdw_b,
    const float* __restrict__ k3w,   const float* __restrict__ k3b)
{
    extern __shared__ float sm[];                 // [64][10][36]
    __shared__ float s_dw[CKV * 9];
    __shared__ float s_db[CKV];
    __shared__ float s_w3[9 * CKV];
    __shared__ float s_b3[9];

    const int t = threadIdx.x;
    for (int i = t; i < CKV * 9; i += 256) { s_dw[i] = kdw_w[i]; s_w3[i] = k3w[i]; }
    if (t < CKV) s_db[t] = kdw_b[t];
    if (t < 9)   s_b3[t] = k3b[t];

    const int bid  = blockIdx.x;
    const int b    = bid / 36;
    const int tile = bid % 36;
    const int h0   = (tile / 3) * 8;
    const int w0   = (tile % 3) * 32;
    const int ty   = t >> 5, tx = t & 31;

    auto stage = [&](const float* __restrict__ basep) {
        #pragma unroll 1
        for (int g = 0; g < 90; g += 6) {
            float vals[6];
            #pragma unroll
            for (int j = 0; j < 6; j++) {
                int idx = (g + j) * 256 + t;
                int c   = idx / TILE_ELEMS;
                int r2  = idx - c * TILE_ELEMS;
                int rr  = r2 / 36, cc = r2 - rr * 36;
                int gh  = h0 - 1 + rr, gw = w0 - 1 + cc;
                bool ok = (gh >= 0) & (gh < Hh) & (gw >= 0) & (gw < Ww) & (cc < 34);
                vals[j] = ok ? basep[(size_t)c * HWp + gh * Ww + gw] : 0.f;
            }
            #pragma unroll
            for (int j = 0; j < 6; j++) sm[(g + j) * 256 + t] = vals[j];
        }
    };

    stage(g_k1 + (size_t)b * CKV * HWp);
    __syncthreads();

    float logit[9];
    #pragma unroll
    for (int tt = 0; tt < 9; tt++) logit[tt] = s_b3[tt];

    #pragma unroll 4
    for (int c = 0; c < CKV; c++) {
        const float* tp = sm + c * TILE_ELEMS + ty * 36 + tx;
        float dw = s_db[c];
        #pragma unroll
        for (int dy = 0; dy < 3; dy++)
            #pragma unroll
            for (int dx = 0; dx < 3; dx++)
                dw = fmaf(tp[dy * 36 + dx], s_dw[c * 9 + dy * 3 + dx], dw);
        #pragma unroll
        for (int tt = 0; tt < 9; tt++)
            logit[tt] = fmaf(s_w3[tt * CKV + c], dw, logit[tt]);
    }

    float m = logit[0];
    #pragma unroll
    for (int tt = 1; tt < 9; tt++) m = fmaxf(m, logit[tt]);
    float ws[9], s = 0.f;
    #pragma unroll
    for (int tt = 0; tt < 9; tt++) { ws[tt] = __expf(logit[tt] - m); s += ws[tt]; }
    float inv = 1.f / s;
    #pragma unroll
    for (int tt = 0; tt < 9; tt++) ws[tt] *= inv;

    __syncthreads();
    stage(g_v + (size_t)b * CKV * HWp);
    __syncthreads();

    float* yb = g_y + (size_t)b * CKV * HWp + (h0 + ty) * Ww + (w0 + tx);
    #pragma unroll 4
    for (int c = 0; c < CKV; c++) {
        const float* tp = sm + c * TILE_ELEMS + ty * 36 + tx;
        float acc = 0.f;
        #pragma unroll
        for (int dy = 0; dy < 3; dy++)
            #pragma unroll
            for (int dx = 0; dx < 3; dx++)
                acc = fmaf(ws[dy * 3 + dx], tp[dy * 36 + dx], acc);
        yb[(size_t)c * HWp] = acc;
    }
}

// ---------------------------------------------------------------------------
// Kernel 3: out 1x1 conv (512 co) + residual. D[128co][128pix], K=64, tf32 mma.
//   R8: smem-staged epilogue — fully coalesced 512B/warp x-read + out-write.
//   grid = (576, 4), block = 256, dyn smem = 69696
// ---------------------------------------------------------------------------
#define EPI_STRIDE 132                    // padded row stride in floats
#define OUT_SMEM   (128 * EPI_STRIDE * 4) // 67584 B

__global__ __launch_bounds__(256) void out_mma(
    const float* __restrict__ x,
    const float* __restrict__ ow, const float* __restrict__ ob,
    float* __restrict__ out)
{
    extern __shared__ char smem[];
    const uint32_t sb = smem_u32(smem);

    const int t = threadIdx.x, warp = t >> 5, lane = t & 31;
    const int b = blockIdx.x / 72, hw0 = (blockIdx.x % 72) * 128;
    const int co0 = blockIdx.y * 128;
    const float* yb = g_y + (size_t)b * CKV * HWp + hw0;

    const int arow = t >> 1, aq0 = (t & 1) * 4;
    const float* awsrc = ow + (size_t)(co0 + arow) * CKV;
    const int bp = t & 127, bq0 = (t >> 7) * 4;
    const int wm = (warp & 1) * 64, wn = (warp >> 1) * 32;

    float acc[4][4][4];
    #pragma unroll
    for (int i = 0; i < 4; i++)
        #pragma unroll
        for (int j = 0; j < 4; j++)
            #pragma unroll
            for (int q = 0; q < 4; q++) acc[i][j][q] = 0.f;

    float pa[16], pb[16];
    auto loadA = [&](int k0) {
        #pragma unroll
        for (int i = 0; i < 4; i++) {
            float4 v = *(const float4*)(awsrc + k0 + (aq0 + i) * 4);
            pa[i*4+0] = v.x; pa[i*4+1] = v.y; pa[i*4+2] = v.z; pa[i*4+3] = v.w;
        }
    };
    auto loadB = [&](int k0) {
        #pragma unroll
        for (int i = 0; i < 4; i++) {
            const float* s = yb + (size_t)(k0 + (bq0 + i) * 4) * HWp + bp;
            pb[i*4+0] = s[0]; pb[i*4+1] = s[HWp]; pb[i*4+2] = s[2*HWp]; pb[i*4+3] = s[3*HWp];
        }
    };
    auto store = [&](int buf) {
        uint32_t sA = sb + (uint32_t)buf * 32768u;
        uint32_t sB = sA + 16384u;
        #pragma unroll
        for (int i = 0; i < 4; i++) {
            sts128(swaddr(sA, arow, (aq0 + i) * 4),
                   f2tf32(pa[i*4+0]), f2tf32(pa[i*4+1]), f2tf32(pa[i*4+2]), f2tf32(pa[i*4+3]));
            sts128(swaddr(sB, bp, (bq0 + i) * 4),
                   f2tf32(pb[i*4+0]), f2tf32(pb[i*4+1]), f2tf32(pb[i*4+2]), f2tf32(pb[i*4+3]));
        }
    };
    auto compute = [&](int buf) {
        uint32_t sA = sb + (uint32_t)buf * 32768u;
        uint32_t sB = sA + 16384u;
        #pragma unroll
        for (int ks = 0; ks < 4; ks++) {
            const int kb = ks * 8;
            uint32_t af[4][4], bf[4][2];
            #pragma unroll
            for (int mi = 0; mi < 4; mi++) {
                int r = wm + mi * 16 + (lane >> 2);
                int c = kb + (lane & 3);
                af[mi][0] = lds32(swaddr(sA, r,     c));
                af[mi][1] = lds32(swaddr(sA, r + 8, c));
                af[mi][2] = lds32(swaddr(sA, r,     c + 4));
                af[mi][3] = lds32(swaddr(sA, r + 8, c + 4));
            }
            #pragma unroll
            for (int ni = 0; ni < 4; ni++) {
                int n = wn + ni * 8 + (lane >> 2);
                int c = kb + (lane & 3);
                bf[ni][0] = lds32(swaddr(sB, n, c));
                bf[ni][1] = lds32(swaddr(sB, n, c + 4));
            }
            #pragma unroll
            for (int mi = 0; mi < 4; mi++)
                #pragma unroll
                for (int ni = 0; ni < 4; ni++)
                    mma_tf32(acc[mi][ni], af[mi], bf[ni]);
        }
    };

    loadA(0); loadB(0); store(0);
    __syncthreads();
    for (int ck = 0; ck < 2; ck++) {
        if (ck < 1) { loadA(32); loadB(32); }
        compute(ck & 1);
        if (ck < 1) store(1);
        __syncthreads();
    }

    // ---- R8 epilogue: stage acc -> smem [128co][132], then coalesced I/O ----
    float* sme = (float*)smem;
    #pragma unroll
    for (int mi = 0; mi < 4; mi++) {
        #pragma unroll
        for (int h = 0; h < 2; h++) {
            const int co = wm + mi * 16 + (lane >> 2) + h * 8;
            #pragma unroll
            for (int ni = 0; ni < 4; ni++) {
                const int px = wn + ni * 8 + (lane & 3) * 2;
                float2 v = make_float2(acc[mi][ni][h*2+0], acc[mi][ni][h*2+1]);
                *(float2*)(sme + co * EPI_STRIDE + px) = v;
            }
        }
    }
    __syncthreads();

    // Each warp walks 16 co-rows; lane covers 4 consecutive pixels (float4).
    #pragma unroll 4
    for (int it = 0; it < 16; it++) {
        const int r   = warp * 16 + it;
        const int co  = co0 + r;
        const float bias = ob[co];
        const size_t gidx = ((size_t)b * Cc + co) * HWp + hw0 + lane * 4;
        float4 sv = *(float4*)(sme + r * EPI_STRIDE + lane * 4);
        float4 xv = *(const float4*)(x + gidx);
        float4 o;
        o.x = xv.x + bias + sv.x;
        o.y = xv.y + bias + sv.y;
        o.z = xv.z + bias + sv.z;
        o.w = xv.w + bias + sv.w;
        *(float4*)(out + gidx) = o;
    }
}

// ---------------------------------------------------------------------------
extern "C" void kernel_launch(void* const* d_in, const int* in_sizes, int n_in,
                              void* d_out, int out_size)
{
    const float* x      = (const float*)d_in[0];
    const float* key1_w = (const float*)d_in[1];
    const float* key1_b = (const float*)d_in[2];
    const float* kdw_w  = (const float*)d_in[3];
    const float* kdw_b  = (const float*)d_in[4];
    const float* key3_w = (const float*)d_in[5];
    const float* key3_b = (const float*)d_in[6];
    const float* val_w  = (const float*)d_in[7];
    const float* val_b  = (const float*)d_in[8];
    const float* out_w  = (const float*)d_in[9];
    const float* out_b  = (const float*)d_in[10];
    float* out = (float*)d_out;

    static bool attr_set = false;
    if (!attr_set) {
        cudaFuncSetAttribute(k1v_mma,   cudaFuncAttributeMaxDynamicSharedMemorySize, 65536);
        cudaFuncSetAttribute(out_mma,   cudaFuncAttributeMaxDynamicSharedMemorySize, OUT_SMEM);
        cudaFuncSetAttribute(mid_fused, cudaFuncAttributeMaxDynamicSharedMemorySize, SMEM_MID * 4);
        attr_set = true;
    }

    k1v_mma<<<576, 256, 65536>>>(x, key1_w, key1_b, val_w, val_b);
    mid_fused<<<Bz * 36, 256, SMEM_MID * 4>>>(kdw_w, kdw_b, key3_w, key3_b);
    out_mma<<<dim3(576, 4), 256, OUT_SMEM>>>(x, out_w, out_b, out);
}